// round 1
// baseline (speedup 1.0000x reference)
#include <cuda_runtime.h>
#include <math.h>

#define E 1024
#define NH 16
#define P 64
#define BATCH 2
#define SEQ 2048
#define BS (BATCH*SEQ)          // 4096
#define QKV_LD 192

// ---------------- device scratch (no allocations allowed) ----------------
__device__ float g_lam;
__device__ float g_Wf[E*QKV_LD];       // [1024,192]  fused proj weights (q|k|v)
__device__ float g_Weff[P*E];          // [64,1024]   head-collapsed result weight
__device__ float g_qkv[BS*QKV_LD];     // [4096,192]  q|k|v
__device__ float g_M[BATCH*P*P];       // [2,64,64]   K^T V
__device__ float g_G[BATCH*P*E];       // [2,64,1024] D * M * Weff

// ---------------- K1: lambda scalar + zero M ----------------
__global__ void k_scalars(const float* __restrict__ q1v, const float* __restrict__ k1v,
                          const float* __restrict__ q2v, const float* __restrict__ k2v,
                          const float* __restrict__ lam0)
{
    __shared__ float s1[256], s2[256];
    int t = threadIdx.x;
    float a = 0.f, b = 0.f;
    for (int i = t; i < E; i += 256) {
        a = fmaf(q1v[i], k1v[i], a);
        b = fmaf(q2v[i], k2v[i], b);
    }
    s1[t] = a; s2[t] = b; __syncthreads();
    for (int o = 128; o > 0; o >>= 1) {
        if (t < o) { s1[t] += s1[t+o]; s2[t] += s2[t+o]; }
        __syncthreads();
    }
    if (t == 0) g_lam = expf(s1[0]) - expf(s2[0]) + lam0[0];
    for (int i = t; i < BATCH*P*P; i += 256) g_M[i] = 0.f;
}

// ---------------- generic tiled SGEMM: C[M,N] = A[M,K]@B[K,N] (+bias) ----------------
// BM=BN=64, BK=16, 256 threads, 4x4 microtile. All dims multiples of tile.
__global__ void sgemm64(const float* __restrict__ A, int lda,
                        const float* __restrict__ B, int ldb,
                        float* __restrict__ C, int ldc,
                        int K,
                        const float* __restrict__ bias, int bias_mod)
{
    __shared__ float As[16][68];   // [k][m], padded to 68 (bank spread, 16B aligned rows)
    __shared__ float Bs[16][64];   // [k][n]
    const int row0 = blockIdx.y * 64;
    const int col0 = blockIdx.x * 64;
    const int tid = threadIdx.x;
    const int ty = tid >> 4, tx = tid & 15;

    float acc[4][4] = {};

    for (int k0 = 0; k0 < K; k0 += 16) {
        #pragma unroll
        for (int i = 0; i < 4; i++) {
            int idx = tid + i * 256;            // 1024 elems
            int r = idx >> 4, c = idx & 15;
            As[c][r] = A[(size_t)(row0 + r) * lda + k0 + c];
        }
        #pragma unroll
        for (int i = 0; i < 4; i++) {
            int idx = tid + i * 256;
            int kr = idx >> 6, nc = idx & 63;
            Bs[kr][nc] = B[(size_t)(k0 + kr) * ldb + col0 + nc];
        }
        __syncthreads();
        #pragma unroll
        for (int kk = 0; kk < 16; kk++) {
            float4 a4 = *(const float4*)&As[kk][ty * 4];
            float4 b4 = *(const float4*)&Bs[kk][tx * 4];
            float av[4] = {a4.x, a4.y, a4.z, a4.w};
            float bv[4] = {b4.x, b4.y, b4.z, b4.w};
            #pragma unroll
            for (int i = 0; i < 4; i++)
                #pragma unroll
                for (int j = 0; j < 4; j++)
                    acc[i][j] = fmaf(av[i], bv[j], acc[i][j]);
        }
        __syncthreads();
    }

    #pragma unroll
    for (int i = 0; i < 4; i++) {
        int r = row0 + ty * 4 + i;
        int cbase = col0 + tx * 4;
        float4 o;
        float* po = (float*)&o;
        #pragma unroll
        for (int j = 0; j < 4; j++) {
            float v = acc[i][j];
            if (bias) v += bias[(cbase + j) % bias_mod];
            po[j] = v;
        }
        *(float4*)&C[(size_t)r * ldc + cbase] = o;
    }
}

// ---------------- K2b: Weff[q][e] = sum_h (h+1) * RW[h*64+q][e] ----------------
__global__ void k_weff(const float* __restrict__ RW)
{
    int idx = blockIdx.x * 256 + threadIdx.x;    // 65536 total
    int q = idx >> 10, e = idx & 1023;
    float s = 0.f;
    #pragma unroll
    for (int h = 0; h < NH; h++)
        s = fmaf((float)(h + 1), RW[(size_t)((h << 6) + q) * E + e], s);
    g_Weff[idx] = s;
}

// ---------------- K4: M_b += k_chunk^T @ v_chunk ----------------
// grid (32, BATCH), 256 threads, chunk of 64 tokens
__global__ void k_ktv()
{
    __shared__ float ks[64][64];
    __shared__ float vs[64][64];
    const int b = blockIdx.y;
    const int t0 = blockIdx.x * 64;
    const int tid = threadIdx.x;
    const float* base = g_qkv + (size_t)(b * SEQ + t0) * QKV_LD;

    #pragma unroll
    for (int i = 0; i < 16; i++) {
        int idx = tid + i * 256;
        int t = idx >> 6, c = idx & 63;
        ks[t][c] = base[t * QKV_LD + 64 + c];
        vs[t][c] = base[t * QKV_LD + 128 + c];
    }
    __syncthreads();

    const int ty = tid >> 4, tx = tid & 15;
    float acc[4][4] = {};
    #pragma unroll 4
    for (int t = 0; t < 64; t++) {
        float4 a4 = *(const float4*)&ks[t][ty * 4];
        float4 b4 = *(const float4*)&vs[t][tx * 4];
        float av[4] = {a4.x, a4.y, a4.z, a4.w};
        float bv[4] = {b4.x, b4.y, b4.z, b4.w};
        #pragma unroll
        for (int i = 0; i < 4; i++)
            #pragma unroll
            for (int j = 0; j < 4; j++)
                acc[i][j] = fmaf(av[i], bv[j], acc[i][j]);
    }
    float* M = g_M + b * P * P;
    #pragma unroll
    for (int i = 0; i < 4; i++)
        #pragma unroll
        for (int j = 0; j < 4; j++)
            atomicAdd(&M[(ty * 4 + i) * P + tx * 4 + j], acc[i][j]);
}

// ---------------- K5: G_b[p][e] = s_p * sum_q M_b[p][q] * Weff[q][e] ----------------
// grid (16 e-tiles, BATCH), 256 threads
__global__ void k_G()
{
    __shared__ float MsT[64][68];  // MsT[q][p]
    __shared__ float Ws[64][64];   // Weff tile [q][e]
    const int b = blockIdx.y;
    const int e0 = blockIdx.x * 64;
    const int tid = threadIdx.x;
    const float* M = g_M + b * P * P;

    #pragma unroll
    for (int i = 0; i < 16; i++) {
        int idx = tid + i * 256;
        int p = idx >> 6, q = idx & 63;
        MsT[q][p] = M[p * P + q];
        int qw = idx >> 6, ew = idx & 63;
        Ws[qw][ew] = g_Weff[qw * E + e0 + ew];
    }
    __syncthreads();

    const float lam = g_lam;
    const float scale = 0.125f;             // 1/sqrt(head_dim=64)
    const int ty = tid >> 4, tx = tid & 15;

    float acc[4][4] = {};
    #pragma unroll 4
    for (int q = 0; q < 64; q++) {
        float4 a4 = *(const float4*)&MsT[q][ty * 4];
        float4 b4 = *(const float4*)&Ws[q][tx * 4];
        float av[4] = {a4.x, a4.y, a4.z, a4.w};
        float bv[4] = {b4.x, b4.y, b4.z, b4.w};
        #pragma unroll
        for (int i = 0; i < 4; i++)
            #pragma unroll
            for (int j = 0; j < 4; j++)
                acc[i][j] = fmaf(av[i], bv[j], acc[i][j]);
    }
    float* G = g_G + (size_t)b * P * E;
    #pragma unroll
    for (int i = 0; i < 4; i++) {
        int p = ty * 4 + i;
        float sp = (p < 32) ? scale : (-lam * scale);
        float4 o;
        float* po = (float*)&o;
        #pragma unroll
        for (int j = 0; j < 4; j++) po[j] = sp * acc[i][j];
        *(float4*)&G[(size_t)p * E + e0 + tx * 4] = o;
    }
}

// ---------------- launch ----------------
extern "C" void kernel_launch(void* const* d_in, const int* in_sizes, int n_in,
                              void* d_out, int out_size)
{
    const float* x    = (const float*)d_in[0];
    const float* WQ   = (const float*)d_in[1];
    const float* WK   = (const float*)d_in[2];
    const float* WV   = (const float*)d_in[3];
    const float* RW   = (const float*)d_in[4];
    const float* pw   = (const float*)d_in[5];
    const float* pb   = (const float*)d_in[6];
    const float* q1v  = (const float*)d_in[7];
    const float* k1v  = (const float*)d_in[8];
    const float* q2v  = (const float*)d_in[9];
    const float* k2v  = (const float*)d_in[10];
    const float* lam0 = (const float*)d_in[11];
    float* out = (float*)d_out;

    float *Wf, *Weff_, *qkv, *G;
    cudaGetSymbolAddress((void**)&Wf,    g_Wf);
    cudaGetSymbolAddress((void**)&Weff_, g_Weff);
    cudaGetSymbolAddress((void**)&qkv,   g_qkv);
    cudaGetSymbolAddress((void**)&G,     g_G);

    // K1: lambda + zero M
    k_scalars<<<1, 256>>>(q1v, k1v, q2v, k2v, lam0);

    // K2: Wf[:,0:64]=WQ@pw, [:,64:128]=WK@pw, [:,128:192]=WV@pw
    sgemm64<<<dim3(1, 16), 256>>>(WQ, E, pw, P, Wf + 0,   QKV_LD, E, nullptr, 1);
    sgemm64<<<dim3(1, 16), 256>>>(WK, E, pw, P, Wf + 64,  QKV_LD, E, nullptr, 1);
    sgemm64<<<dim3(1, 16), 256>>>(WV, E, pw, P, Wf + 128, QKV_LD, E, nullptr, 1);

    // K2b: Weff
    k_weff<<<256, 256>>>(RW);

    // K3: qkv = x @ Wf + bias(broadcast per 64)
    sgemm64<<<dim3(3, 64), 256>>>(x, E, Wf, QKV_LD, qkv, QKV_LD, E, pb, 64);

    // K4: M_b = k_b^T v_b
    k_ktv<<<dim3(32, BATCH), 256>>>();

    // K5: G_b = D * M_b * Weff
    k_G<<<dim3(16, BATCH), 256>>>();

    // K6: out_b = q_b @ G_b
    for (int b = 0; b < BATCH; b++) {
        sgemm64<<<dim3(16, 32), 256>>>(qkv + (size_t)b * SEQ * QKV_LD, QKV_LD,
                                       G + (size_t)b * P * E, E,
                                       out + (size_t)b * SEQ * E, E,
                                       P, nullptr, 1);
    }
    (void)in_sizes; (void)n_in; (void)out_size;
}

// round 2
// speedup vs baseline: 1.6544x; 1.6544x over previous
#include <cuda_runtime.h>
#include <math.h>

#define E 1024
#define NH 16
#define P 64
#define BATCH 2
#define SEQ 2048
#define BS (BATCH*SEQ)          // 4096
#define QKV_LD 192

// ---------------- device scratch (no allocations allowed) ----------------
__device__ float g_lam;
__device__ float g_Wf[E*QKV_LD];       // [1024,192]  fused proj weights (q|k|v)
__device__ float g_Weff[P*E];          // [64,1024]   head-collapsed result weight
__device__ float g_qkv[BS*QKV_LD];     // [4096,192]  q|k|v
__device__ float g_M[BATCH*P*P];       // [2,64,64]   K^T V
__device__ float g_G[BATCH*P*E];       // [2,64,1024] D * M * Weff

// ================= fused prep kernel =================
// blocks [0,192):   Wf tiles  (64 row-tiles x 3 matrices)
// blocks [192,448): Weff      (256 blocks)
// block  448:       lambda scalar + zero g_M
__global__ void k_prep(const float* __restrict__ WQ, const float* __restrict__ WK,
                       const float* __restrict__ WV, const float* __restrict__ pw,
                       const float* __restrict__ RW,
                       const float* __restrict__ q1v, const float* __restrict__ k1v,
                       const float* __restrict__ q2v, const float* __restrict__ k2v,
                       const float* __restrict__ lam0)
{
    const int bid = blockIdx.x;
    const int tid = threadIdx.x;

    if (bid < 192) {
        // ---- Wf = W @ pw, 16x64 output tile, K=1024 ----
        __shared__ float As[32][17];   // [k][row]
        __shared__ float Bs[32][64];   // [k][col]
        const int mat  = bid >> 6;          // 0..2
        const int row0 = (bid & 63) * 16;
        const float* A = (mat == 0) ? WQ : (mat == 1) ? WK : WV;
        const int r  = tid >> 4;            // 0..15
        const int c4 = (tid & 15) * 4;      // 0..60

        float acc0 = 0.f, acc1 = 0.f, acc2 = 0.f, acc3 = 0.f;
        for (int k0 = 0; k0 < E; k0 += 32) {
            #pragma unroll
            for (int i = 0; i < 2; i++) {           // A: 16x32
                int idx = tid + i * 256;
                int rr = idx >> 5, kk = idx & 31;
                As[kk][rr] = A[(size_t)(row0 + rr) * E + k0 + kk];
            }
            #pragma unroll
            for (int i = 0; i < 8; i++) {           // B: 32x64
                int idx = tid + i * 256;
                int kk = idx >> 6, nn = idx & 63;
                Bs[kk][nn] = pw[(size_t)(k0 + kk) * P + nn];
            }
            __syncthreads();
            #pragma unroll
            for (int kk = 0; kk < 32; kk++) {
                float a = As[kk][r];
                float4 b = *(const float4*)&Bs[kk][c4];
                acc0 = fmaf(a, b.x, acc0);
                acc1 = fmaf(a, b.y, acc1);
                acc2 = fmaf(a, b.z, acc2);
                acc3 = fmaf(a, b.w, acc3);
            }
            __syncthreads();
        }
        float* o = g_Wf + (size_t)(row0 + r) * QKV_LD + mat * 64 + c4;
        *(float4*)o = make_float4(acc0, acc1, acc2, acc3);
    } else if (bid < 448) {
        // ---- Weff[q][e] = sum_h (h+1) * RW[h*64+q][e] ----
        int idx = (bid - 192) * 256 + tid;          // 65536 total
        int q = idx >> 10, e = idx & 1023;
        float s = 0.f;
        #pragma unroll
        for (int h = 0; h < NH; h++)
            s = fmaf((float)(h + 1), RW[(size_t)((h << 6) + q) * E + e], s);
        g_Weff[idx] = s;
    } else {
        // ---- lambda + zero M ----
        __shared__ float s1[256], s2[256];
        float a = 0.f, b = 0.f;
        for (int i = tid; i < E; i += 256) {
            a = fmaf(q1v[i], k1v[i], a);
            b = fmaf(q2v[i], k2v[i], b);
        }
        s1[tid] = a; s2[tid] = b; __syncthreads();
        for (int o = 128; o > 0; o >>= 1) {
            if (tid < o) { s1[tid] += s1[tid+o]; s2[tid] += s2[tid+o]; }
            __syncthreads();
        }
        if (tid == 0) g_lam = expf(s1[0]) - expf(s2[0]) + lam0[0];
        for (int i = tid; i < BATCH*P*P; i += 256) g_M[i] = 0.f;
    }
}

// ---------------- generic tiled SGEMM: C[M,N] = A[M,K]@B[K,N] (+bias) ----------------
// BM=BN=64, BK=16, 256 threads, 4x4 microtile. blockIdx.z batches via strides.
__global__ void sgemm64(const float* __restrict__ A, int lda, size_t strideA,
                        const float* __restrict__ B, int ldb, size_t strideB,
                        float* __restrict__ C, int ldc, size_t strideC,
                        int K,
                        const float* __restrict__ bias, int bias_mod)
{
    __shared__ float As[16][68];   // [k][m]
    __shared__ float Bs[16][64];   // [k][n]
    A += blockIdx.z * strideA;
    B += blockIdx.z * strideB;
    C += blockIdx.z * strideC;
    const int row0 = blockIdx.y * 64;
    const int col0 = blockIdx.x * 64;
    const int tid = threadIdx.x;
    const int ty = tid >> 4, tx = tid & 15;

    float acc[4][4] = {};

    for (int k0 = 0; k0 < K; k0 += 16) {
        #pragma unroll
        for (int i = 0; i < 4; i++) {
            int idx = tid + i * 256;
            int r = idx >> 4, c = idx & 15;
            As[c][r] = A[(size_t)(row0 + r) * lda + k0 + c];
        }
        #pragma unroll
        for (int i = 0; i < 4; i++) {
            int idx = tid + i * 256;
            int kr = idx >> 6, nc = idx & 63;
            Bs[kr][nc] = B[(size_t)(k0 + kr) * ldb + col0 + nc];
        }
        __syncthreads();
        #pragma unroll
        for (int kk = 0; kk < 16; kk++) {
            float4 a4 = *(const float4*)&As[kk][ty * 4];
            float4 b4 = *(const float4*)&Bs[kk][tx * 4];
            float av[4] = {a4.x, a4.y, a4.z, a4.w};
            float bv[4] = {b4.x, b4.y, b4.z, b4.w};
            #pragma unroll
            for (int i = 0; i < 4; i++)
                #pragma unroll
                for (int j = 0; j < 4; j++)
                    acc[i][j] = fmaf(av[i], bv[j], acc[i][j]);
        }
        __syncthreads();
    }

    #pragma unroll
    for (int i = 0; i < 4; i++) {
        int r = row0 + ty * 4 + i;
        int cbase = col0 + tx * 4;
        float4 o;
        float* po = (float*)&o;
        #pragma unroll
        for (int j = 0; j < 4; j++) {
            float v = acc[i][j];
            if (bias) v += bias[(cbase + j) % bias_mod];
            po[j] = v;
        }
        *(float4*)&C[(size_t)r * ldc + cbase] = o;
    }
}

// ---------------- K4: M_b += k_chunk^T @ v_chunk ----------------
__global__ void k_ktv()
{
    __shared__ float ks[64][64];
    __shared__ float vs[64][64];
    const int b = blockIdx.y;
    const int t0 = blockIdx.x * 64;
    const int tid = threadIdx.x;
    const float* base = g_qkv + (size_t)(b * SEQ + t0) * QKV_LD;

    #pragma unroll
    for (int i = 0; i < 16; i++) {
        int idx = tid + i * 256;
        int t = idx >> 6, c = idx & 63;
        ks[t][c] = base[t * QKV_LD + 64 + c];
        vs[t][c] = base[t * QKV_LD + 128 + c];
    }
    __syncthreads();

    const int ty = tid >> 4, tx = tid & 15;
    float acc[4][4] = {};
    #pragma unroll 4
    for (int t = 0; t < 64; t++) {
        float4 a4 = *(const float4*)&ks[t][ty * 4];
        float4 b4 = *(const float4*)&vs[t][tx * 4];
        float av[4] = {a4.x, a4.y, a4.z, a4.w};
        float bv[4] = {b4.x, b4.y, b4.z, b4.w};
        #pragma unroll
        for (int i = 0; i < 4; i++)
            #pragma unroll
            for (int j = 0; j < 4; j++)
                acc[i][j] = fmaf(av[i], bv[j], acc[i][j]);
    }
    float* M = g_M + b * P * P;
    #pragma unroll
    for (int i = 0; i < 4; i++)
        #pragma unroll
        for (int j = 0; j < 4; j++)
            atomicAdd(&M[(ty * 4 + i) * P + tx * 4 + j], acc[i][j]);
}

// ---------------- K5: G_b[p][e] = s_p * sum_q M_b[p][q] * Weff[q][e] ----------------
__global__ void k_G()
{
    __shared__ float MsT[64][68];  // MsT[q][p]
    __shared__ float Ws[64][64];   // Weff tile [q][e]
    const int b = blockIdx.y;
    const int e0 = blockIdx.x * 64;
    const int tid = threadIdx.x;
    const float* M = g_M + b * P * P;

    #pragma unroll
    for (int i = 0; i < 16; i++) {
        int idx = tid + i * 256;
        int p = idx >> 6, q = idx & 63;
        MsT[q][p] = M[p * P + q];
        Ws[p][q] = g_Weff[p * E + e0 + q];   // p is k-index here, q is e-col
    }
    __syncthreads();

    const float lam = g_lam;
    const float scale = 0.125f;             // 1/sqrt(head_dim=64)
    const int ty = tid >> 4, tx = tid & 15;

    float acc[4][4] = {};
    #pragma unroll 4
    for (int q = 0; q < 64; q++) {
        float4 a4 = *(const float4*)&MsT[q][ty * 4];
        float4 b4 = *(const float4*)&Ws[q][tx * 4];
        float av[4] = {a4.x, a4.y, a4.z, a4.w};
        float bv[4] = {b4.x, b4.y, b4.z, b4.w};
        #pragma unroll
        for (int i = 0; i < 4; i++)
            #pragma unroll
            for (int j = 0; j < 4; j++)
                acc[i][j] = fmaf(av[i], bv[j], acc[i][j]);
    }
    float* G = g_G + (size_t)b * P * E;
    #pragma unroll
    for (int i = 0; i < 4; i++) {
        int p = ty * 4 + i;
        float sp = (p < 32) ? scale : (-lam * scale);
        float4 o;
        float* po = (float*)&o;
        #pragma unroll
        for (int j = 0; j < 4; j++) po[j] = sp * acc[i][j];
        *(float4*)&G[(size_t)p * E + e0 + tx * 4] = o;
    }
}

// ---------------- launch ----------------
extern "C" void kernel_launch(void* const* d_in, const int* in_sizes, int n_in,
                              void* d_out, int out_size)
{
    const float* x    = (const float*)d_in[0];
    const float* WQ   = (const float*)d_in[1];
    const float* WK   = (const float*)d_in[2];
    const float* WV   = (const float*)d_in[3];
    const float* RW   = (const float*)d_in[4];
    const float* pw   = (const float*)d_in[5];
    const float* pb   = (const float*)d_in[6];
    const float* q1v  = (const float*)d_in[7];
    const float* k1v  = (const float*)d_in[8];
    const float* q2v  = (const float*)d_in[9];
    const float* k2v  = (const float*)d_in[10];
    const float* lam0 = (const float*)d_in[11];
    float* out = (float*)d_out;

    float *Wf, *qkv, *G;
    cudaGetSymbolAddress((void**)&Wf,  g_Wf);
    cudaGetSymbolAddress((void**)&qkv, g_qkv);
    cudaGetSymbolAddress((void**)&G,   g_G);

    // K1: all precompute in one launch (Wf, Weff, lambda, zero-M)
    k_prep<<<449, 256>>>(WQ, WK, WV, pw, RW, q1v, k1v, q2v, k2v, lam0);

    // K3: qkv = x @ Wf + bias(broadcast per 64)
    sgemm64<<<dim3(3, 64, 1), 256>>>(x, E, 0, Wf, QKV_LD, 0,
                                     qkv, QKV_LD, 0, E, pb, 64);

    // K4: M_b = k_b^T v_b
    k_ktv<<<dim3(32, BATCH), 256>>>();

    // K5: G_b = D * M_b * Weff
    k_G<<<dim3(16, BATCH), 256>>>();

    // K6: out_b = q_b @ G_b   (batched over z)
    sgemm64<<<dim3(16, 32, BATCH), 256>>>(qkv, QKV_LD, (size_t)SEQ * QKV_LD,
                                          G, E, (size_t)P * E,
                                          out, E, (size_t)SEQ * E,
                                          P, nullptr, 1);
    (void)in_sizes; (void)n_in; (void)out_size;
}

// round 3
// speedup vs baseline: 1.8134x; 1.0961x over previous
#include <cuda_runtime.h>
#include <math.h>
#include <stdint.h>

#define E 1024
#define NH 16
#define P 64
#define BATCH 2
#define SEQ 2048
#define BS (BATCH*SEQ)          // 4096
#define QKV_LD 192

// ---------------- device scratch ----------------
__device__ float g_lam;
__device__ float g_Wf[E*QKV_LD];       // [1024,192]
__device__ float g_Weff[P*E];          // [64,1024]
__device__ float g_qkv[BS*QKV_LD];     // [4096,192]
__device__ float g_M[BATCH*P*P];       // [2,64,64]
__device__ float g_qp[BS*P];           // [4096,64]  q' = (q D) @ M_b

// ---------------- helpers ----------------
__device__ __forceinline__ uint32_t f2tf(float x) {
    uint32_t r;
    asm("cvt.rna.tf32.f32 %0, %1;" : "=r"(r) : "f"(x));
    return r;
}
__device__ __forceinline__ void split_tf32(float x, uint32_t& hi, uint32_t& lo) {
    hi = f2tf(x);
    lo = f2tf(x - __uint_as_float(hi));
}
#define MMA_TF32(d, a, b) \
    asm volatile("mma.sync.aligned.m16n8k8.row.col.f32.tf32.tf32.f32 " \
        "{%0,%1,%2,%3}, {%4,%5,%6,%7}, {%8,%9}, {%0,%1,%2,%3};" \
        : "+f"(d[0]), "+f"(d[1]), "+f"(d[2]), "+f"(d[3]) \
        : "r"(a[0]), "r"(a[1]), "r"(a[2]), "r"(a[3]), "r"(b[0]), "r"(b[1]))

// ================= misc: Weff + lambda + zero M =================
// blocks [0,256): Weff ;  block 256: lambda + zero M
__global__ void k_misc(const float* __restrict__ RW,
                       const float* __restrict__ q1v, const float* __restrict__ k1v,
                       const float* __restrict__ q2v, const float* __restrict__ k2v,
                       const float* __restrict__ lam0)
{
    const int bid = blockIdx.x;
    const int tid = threadIdx.x;
    if (bid < 256) {
        int idx = bid * 256 + tid;                 // 65536 total
        int q = idx >> 10, e = idx & 1023;
        float s = 0.f;
        #pragma unroll
        for (int h = 0; h < NH; h++)
            s = fmaf((float)(h + 1), RW[(size_t)((h << 6) + q) * E + e], s);
        g_Weff[idx] = s;
    } else {
        __shared__ float s1[256], s2[256];
        float a = 0.f, b = 0.f;
        for (int i = tid; i < E; i += 256) {
            a = fmaf(q1v[i], k1v[i], a);
            b = fmaf(q2v[i], k2v[i], b);
        }
        s1[tid] = a; s2[tid] = b; __syncthreads();
        for (int o = 128; o > 0; o >>= 1) {
            if (tid < o) { s1[tid] += s1[tid+o]; s2[tid] += s2[tid+o]; }
            __syncthreads();
        }
        if (tid == 0) g_lam = expf(s1[0]) - expf(s2[0]) + lam0[0];
        for (int i = tid; i < BATCH*P*P; i += 256) g_M[i] = 0.f;
    }
}

// ================= generic tensor-core GEMM (3xTF32) =================
// C[M,N] = A[M,K] @ B[K,N], all row-major fp32. Block tile 128x64, BK=16.
// 256 threads = 8 warps (4 m-warps x 2 n-warps), warp tile 32x32 = 2x4 mma m16n8k8.
// mode 0: A = A0 + z*strideA, B += z*strideB, C += z*strideC
// mode 1: A = {A0,A1,A2}[z], C += z*64 (column pack into Wf)
// mode 2: like 0, but B rows scaled by s_k = (k<32 ? 0.125 : -lam*0.125)
__global__ void __launch_bounds__(256)
mm(const float* __restrict__ A0, const float* __restrict__ A1, const float* __restrict__ A2,
   int lda, size_t strideA,
   const float* __restrict__ B, int ldb, size_t strideB,
   float* __restrict__ C, int ldc, size_t strideC,
   int K, const float* __restrict__ bias, int mode)
{
    __shared__ float As[16][132];   // [k][m]
    __shared__ float Bs[16][68];    // [k][n]

    const int z = blockIdx.z;
    const float* A;
    if (mode == 1) {
        A = (z == 0) ? A0 : (z == 1) ? A1 : A2;
        C += z * 64;
    } else {
        A = A0 + (size_t)z * strideA;
        B += (size_t)z * strideB;
        C += (size_t)z * strideC;
    }
    const int row0 = blockIdx.y * 128;
    const int col0 = blockIdx.x * 64;
    const int tid  = threadIdx.x;
    const int wid  = tid >> 5, lane = tid & 31;
    const int wm = wid & 3, wn = wid >> 2;
    const int g = lane >> 2, t = lane & 3;

    // loader mapping
    const int m_l  = tid >> 1;                 // 0..127
    const int kh_l = (tid & 1) * 8;            // 0 or 8
    const int kb_l = tid >> 4;                 // 0..15
    const int n4_l = (tid & 15) * 4;           // 0..60
    const float* Ap = A + (size_t)(row0 + m_l) * lda + kh_l;
    const float* Bp = B + (size_t)kb_l * ldb + col0 + n4_l;

    const float lam = (mode == 2) ? g_lam : 0.f;

    float acc[2][4][4] = {};

    float4 pa0 = *(const float4*)(Ap);
    float4 pa1 = *(const float4*)(Ap + 4);
    float4 pb  = *(const float4*)(Bp);

    for (int k0 = 0; k0 < K; k0 += 16) {
        // stage into smem
        As[kh_l+0][m_l] = pa0.x; As[kh_l+1][m_l] = pa0.y;
        As[kh_l+2][m_l] = pa0.z; As[kh_l+3][m_l] = pa0.w;
        As[kh_l+4][m_l] = pa1.x; As[kh_l+5][m_l] = pa1.y;
        As[kh_l+6][m_l] = pa1.z; As[kh_l+7][m_l] = pa1.w;
        float4 pbv = pb;
        if (mode == 2) {
            float sp = ((k0 + kb_l) < 32) ? 0.125f : (-lam * 0.125f);
            pbv.x *= sp; pbv.y *= sp; pbv.z *= sp; pbv.w *= sp;
        }
        *(float4*)&Bs[kb_l][n4_l] = pbv;
        __syncthreads();

        if (k0 + 16 < K) {
            pa0 = *(const float4*)(Ap + k0 + 16);
            pa1 = *(const float4*)(Ap + k0 + 20);
            pb  = *(const float4*)(Bp + (size_t)(k0 + 16) * ldb);
        }

        #pragma unroll
        for (int ks = 0; ks < 16; ks += 8) {
            uint32_t ah[2][4], al[2][4];
            #pragma unroll
            for (int mi = 0; mi < 2; mi++) {
                int m0 = wm * 32 + mi * 16 + g;
                split_tf32(As[ks+t  ][m0  ], ah[mi][0], al[mi][0]);
                split_tf32(As[ks+t  ][m0+8], ah[mi][1], al[mi][1]);
                split_tf32(As[ks+t+4][m0  ], ah[mi][2], al[mi][2]);
                split_tf32(As[ks+t+4][m0+8], ah[mi][3], al[mi][3]);
            }
            uint32_t bh[4][2], bl[4][2];
            #pragma unroll
            for (int nj = 0; nj < 4; nj++) {
                int n0 = wn * 32 + nj * 8 + g;
                split_tf32(Bs[ks+t  ][n0], bh[nj][0], bl[nj][0]);
                split_tf32(Bs[ks+t+4][n0], bh[nj][1], bl[nj][1]);
            }
            #pragma unroll
            for (int mi = 0; mi < 2; mi++)
                #pragma unroll
                for (int nj = 0; nj < 4; nj++) {
                    MMA_TF32(acc[mi][nj], ah[mi], bh[nj]);
                    MMA_TF32(acc[mi][nj], al[mi], bh[nj]);
                    MMA_TF32(acc[mi][nj], ah[mi], bl[nj]);
                }
        }
        __syncthreads();
    }

    // epilogue
    #pragma unroll
    for (int mi = 0; mi < 2; mi++) {
        int r0 = row0 + wm * 32 + mi * 16 + g;
        int r1 = r0 + 8;
        #pragma unroll
        for (int nj = 0; nj < 4; nj++) {
            int cl = wn * 32 + nj * 8 + 2 * t;       // column within 64-tile
            int c  = col0 + cl;
            float b0 = 0.f, b1 = 0.f;
            if (bias) { b0 = bias[cl & 63]; b1 = bias[(cl + 1) & 63]; }
            *(float2*)&C[(size_t)r0 * ldc + c] =
                make_float2(acc[mi][nj][0] + b0, acc[mi][nj][1] + b1);
            *(float2*)&C[(size_t)r1 * ldc + c] =
                make_float2(acc[mi][nj][2] + b0, acc[mi][nj][3] + b1);
        }
    }
}

// ================= K^T V accumulation (32-token chunks) =================
__global__ void k_ktv()
{
    __shared__ float ks[32][64];
    __shared__ float vs[32][64];
    const int b = blockIdx.y;
    const int t0 = blockIdx.x * 32;
    const int tid = threadIdx.x;
    const float* base = g_qkv + (size_t)(b * SEQ + t0) * QKV_LD;

    #pragma unroll
    for (int i = 0; i < 8; i++) {
        int idx = tid + i * 256;
        int tt = idx >> 6, c = idx & 63;
        ks[tt][c] = base[tt * QKV_LD + 64 + c];
        vs[tt][c] = base[tt * QKV_LD + 128 + c];
    }
    __syncthreads();

    const int ty = tid >> 4, tx = tid & 15;
    float acc[4][4] = {};
    #pragma unroll 4
    for (int tt = 0; tt < 32; tt++) {
        float4 a4 = *(const float4*)&ks[tt][ty * 4];
        float4 b4 = *(const float4*)&vs[tt][tx * 4];
        float av[4] = {a4.x, a4.y, a4.z, a4.w};
        float bv[4] = {b4.x, b4.y, b4.z, b4.w};
        #pragma unroll
        for (int i = 0; i < 4; i++)
            #pragma unroll
            for (int j = 0; j < 4; j++)
                acc[i][j] = fmaf(av[i], bv[j], acc[i][j]);
    }
    float* M = g_M + b * P * P;
    #pragma unroll
    for (int i = 0; i < 4; i++)
        #pragma unroll
        for (int j = 0; j < 4; j++)
            atomicAdd(&M[(ty * 4 + i) * P + tx * 4 + j], acc[i][j]);
}

// ---------------- launch ----------------
extern "C" void kernel_launch(void* const* d_in, const int* in_sizes, int n_in,
                              void* d_out, int out_size)
{
    const float* x    = (const float*)d_in[0];
    const float* WQ   = (const float*)d_in[1];
    const float* WK   = (const float*)d_in[2];
    const float* WV   = (const float*)d_in[3];
    const float* RW   = (const float*)d_in[4];
    const float* pw   = (const float*)d_in[5];
    const float* pb   = (const float*)d_in[6];
    const float* q1v  = (const float*)d_in[7];
    const float* k1v  = (const float*)d_in[8];
    const float* q2v  = (const float*)d_in[9];
    const float* k2v  = (const float*)d_in[10];
    const float* lam0 = (const float*)d_in[11];
    float* out = (float*)d_out;

    float *Wf, *qkv, *Mb, *qp, *Weff;
    cudaGetSymbolAddress((void**)&Wf,   g_Wf);
    cudaGetSymbolAddress((void**)&qkv,  g_qkv);
    cudaGetSymbolAddress((void**)&Mb,   g_M);
    cudaGetSymbolAddress((void**)&qp,   g_qp);
    cudaGetSymbolAddress((void**)&Weff, g_Weff);

    // 1. Weff + lambda + zero M
    k_misc<<<257, 256>>>(RW, q1v, k1v, q2v, k2v, lam0);

    // 2. Wf[:, z*64:(z+1)*64] = {WQ,WK,WV}[z] @ pw
    mm<<<dim3(1, 8, 3), 256>>>(WQ, WK, WV, E, 0,
                               pw, P, 0,
                               Wf, QKV_LD, 0,
                               E, nullptr, 1);

    // 3. qkv = x @ Wf + bias(mod 64)
    mm<<<dim3(3, 32, 1), 256>>>(x, nullptr, nullptr, E, 0,
                                Wf, QKV_LD, 0,
                                qkv, QKV_LD, 0,
                                E, pb, 0);

    // 4. M_b = k_b^T v_b
    k_ktv<<<dim3(64, BATCH), 256>>>();

    // 5. q'_b = (q_b D) @ M_b   (D folded into B rows)
    mm<<<dim3(1, 16, BATCH), 256>>>(qkv, nullptr, nullptr, QKV_LD, (size_t)SEQ * QKV_LD,
                                    Mb, P, (size_t)P * P,
                                    qp, P, (size_t)SEQ * P,
                                    P, nullptr, 2);

    // 6. out = q' @ Weff   (single un-batched [4096,64]@[64,1024])
    mm<<<dim3(16, 32, 1), 256>>>(qp, nullptr, nullptr, P, 0,
                                 Weff, E, 0,
                                 out, E, 0,
                                 P, nullptr, 0);

    (void)in_sizes; (void)n_in; (void)out_size;
}

// round 4
// speedup vs baseline: 2.7329x; 1.5071x over previous
#include <cuda_runtime.h>
#include <cuda_bf16.h>
#include <math.h>
#include <stdint.h>

#define E 1024
#define NH 16
#define P 64
#define BATCH 2
#define SEQ 2048
#define BS (BATCH*SEQ)          // 4096
#define QKV_LD 192

// ---------------- device scratch ----------------
__device__ float g_lam;
__device__ float g_Wf[E*QKV_LD];       // [1024,192]
__device__ float g_Weff[P*E];          // [64,1024]
__device__ float g_qkv[BS*QKV_LD];     // [4096,192]
__device__ float g_M[BATCH*P*P];       // [2,64,64]
__device__ float g_G[BATCH*P*E];       // [2,64,1024]

// ---------------- helpers ----------------
// split fp32 pair into bf16x2 (hi) + bf16x2 (residual lo); element0 in low half
__device__ __forceinline__ void split2(float x0, float x1, uint32_t& hi, uint32_t& lo) {
    __nv_bfloat162 h = __floats2bfloat162_rn(x0, x1);
    hi = *(uint32_t*)&h;
    __nv_bfloat162 l = __floats2bfloat162_rn(x0 - __bfloat162float(h.x),
                                             x1 - __bfloat162float(h.y));
    lo = *(uint32_t*)&l;
}

#define MMA_BF16(d, a0,a1,a2,a3, b0,b1) \
    asm volatile("mma.sync.aligned.m16n8k16.row.col.f32.bf16.bf16.f32 " \
        "{%0,%1,%2,%3}, {%4,%5,%6,%7}, {%8,%9}, {%0,%1,%2,%3};" \
        : "+f"(d[0]),"+f"(d[1]),"+f"(d[2]),"+f"(d[3]) \
        : "r"(a0),"r"(a1),"r"(a2),"r"(a3), "r"(b0),"r"(b1))

// ================= misc: Weff + lambda + zero M =================
__global__ void k_misc(const float* __restrict__ RW,
                       const float* __restrict__ q1v, const float* __restrict__ k1v,
                       const float* __restrict__ q2v, const float* __restrict__ k2v,
                       const float* __restrict__ lam0)
{
    const int bid = blockIdx.x;
    const int tid = threadIdx.x;
    if (bid < 256) {
        int idx = bid * 256 + tid;                 // 65536 total
        int q = idx >> 10, e = idx & 1023;
        float s = 0.f;
        #pragma unroll
        for (int h = 0; h < NH; h++)
            s = fmaf((float)(h + 1), RW[(size_t)((h << 6) + q) * E + e], s);
        g_Weff[idx] = s;
    } else {
        __shared__ float s1[256], s2[256];
        float a = 0.f, b = 0.f;
        for (int i = tid; i < E; i += 256) {
            a = fmaf(q1v[i], k1v[i], a);
            b = fmaf(q2v[i], k2v[i], b);
        }
        s1[tid] = a; s2[tid] = b; __syncthreads();
        for (int o = 128; o > 0; o >>= 1) {
            if (tid < o) { s1[tid] += s1[tid+o]; s2[tid] += s2[tid+o]; }
            __syncthreads();
        }
        if (tid == 0) g_lam = expf(s1[0]) - expf(s2[0]) + lam0[0];
        for (int i = tid; i < BATCH*P*P; i += 256) g_M[i] = 0.f;
    }
}

// ================= generic bf16-3pass tensor GEMM =================
// C[M,N=64-tile] = A[M,K] @ B[K,N], fp32 in/out, 3x bf16 mma m16n8k16.
// MODE 0: plain (+bias), batched by z via strides
// MODE 1: A chosen from {A0,A1,A2} by z, C += z*64   (Wf pack)
// MODE 2: ktv: A = k^T slice of g_qkv (gather), B = v slice, atomicAdd into g_M
// MODE 3: A rows scaled by s_p = (p<32 ? 0.125 : -lam*0.125)  (G = (D M) Weff)
template<int BM, int MODE, int KT>
__global__ void __launch_bounds__(256) mmk(
    const float* __restrict__ A0, const float* __restrict__ A1, const float* __restrict__ A2,
    int lda, long sA,
    const float* __restrict__ B0, int ldb, long sB,
    float* __restrict__ C, int ldc, long sC,
    const float* __restrict__ bias)
{
    constexpr int AST = (BM == 128) ? 136 : 72;
    __shared__ uint32_t AsH[8][AST], AsL[8][AST];
    __shared__ uint32_t BsH[8][72],  BsL[8][72];

    const int z   = blockIdx.z;
    const int tid = threadIdx.x;

    const float* A = A0;
    const float* B = B0;
    float* Cp = C;
    const float* Aq = nullptr;
    const float* Bq = nullptr;
    int ldbv = ldb;
    if (MODE == 1) {
        A = (z == 0) ? A0 : (z == 1) ? A1 : A2;
        Cp = C + z * 64;
    } else if (MODE == 2) {
        Aq = g_qkv + (long)(z * SEQ + blockIdx.x * 128) * QKV_LD;
        Bq = Aq + 128;
        Cp = C + z * P * P;
        ldbv = QKV_LD;
    } else {
        A  = A0 + (long)z * sA;
        B  = B0 + (long)z * sB;
        Cp = C  + (long)z * sC;
    }
    const int row0 = (MODE == 2) ? 0 : blockIdx.y * BM;
    const int col0 = (MODE == 2) ? 0 : blockIdx.x * 64;

    // warp layout
    constexpr int WM = (BM == 128) ? 4 : 2;
    constexpr int WCOL = 64 / (8 / WM);
    constexpr int NJ = WCOL / 8;
    const int wid = tid >> 5, lane = tid & 31;
    const int wm = wid % WM, wn = wid / WM;
    const int g = lane >> 2, t = lane & 3;
    const int n0 = wn * WCOL;

    // loader mappings
    const int m_l  = (MODE == 2) ? (tid & 63) : ((BM == 128) ? (tid >> 1) : (tid >> 2));
    const int khA  = (MODE == 2) ? ((tid >> 6) * 4) : ((BM == 128) ? (tid & 1) * 8 : (tid & 3) * 4);
    const int khA2 = khA >> 1;
    const int k2b  = tid >> 5;
    const int n2   = (tid & 31) * 2;

    float sclA = 1.f;
    if (MODE == 3) sclA = (m_l < 32) ? 0.125f : (-g_lam * 0.125f);

    constexpr int AR = (BM == 128) ? 8 : 4;
    float rA0[AR], rA1[AR], rB0[4], rB1[4];

    auto ldA = [&](int k0, float* r) {
        int kk = (k0 < KT) ? k0 : 0;
        if (MODE == 2) {
            const float* p = Aq + (long)(kk + khA) * QKV_LD + 64 + m_l;
            #pragma unroll
            for (int j = 0; j < 4; j++) r[j] = p[j * QKV_LD];
        } else if (BM == 128) {
            const float* p = A + (long)(row0 + m_l) * lda + kk + khA;
            float4 v0 = *(const float4*)p;
            float4 v1 = *(const float4*)(p + 4);
            r[0]=v0.x; r[1]=v0.y; r[2]=v0.z; r[3]=v0.w;
            r[4]=v1.x; r[5]=v1.y; r[6]=v1.z; r[7]=v1.w;
        } else {
            float4 v0 = *(const float4*)(A + (long)(row0 + m_l) * lda + kk + khA);
            r[0]=v0.x; r[1]=v0.y; r[2]=v0.z; r[3]=v0.w;
        }
    };
    auto ldB = [&](int k0, float* r) {
        int kk = (k0 < KT) ? k0 : 0;
        const float* bp = (MODE == 2) ? Bq : (B + col0);
        float2 e0 = *(const float2*)(bp + (long)(kk + 2*k2b)     * ldbv + n2);
        float2 e1 = *(const float2*)(bp + (long)(kk + 2*k2b + 1) * ldbv + n2);
        r[0]=e0.x; r[1]=e0.y; r[2]=e1.x; r[3]=e1.y;
    };
    auto stA = [&](const float* r) {
        #pragma unroll
        for (int j = 0; j < AR/2; j++)
            split2(r[2*j] * sclA, r[2*j+1] * sclA, AsH[khA2 + j][m_l], AsL[khA2 + j][m_l]);
    };
    auto stB = [&](const float* r) {
        split2(r[0], r[2], BsH[k2b][n2],   BsL[k2b][n2]);
        split2(r[1], r[3], BsH[k2b][n2+1], BsL[k2b][n2+1]);
    };

    float acc[2][NJ][4] = {};

    auto compute = [&]() {
        uint32_t bH[NJ][2], bL[NJ][2];
        #pragma unroll
        for (int nj = 0; nj < NJ; nj++) {
            int nb = n0 + nj * 8 + g;
            bH[nj][0] = BsH[t][nb]; bH[nj][1] = BsH[t+4][nb];
            bL[nj][0] = BsL[t][nb]; bL[nj][1] = BsL[t+4][nb];
        }
        #pragma unroll
        for (int mi = 0; mi < 2; mi++) {
            int mb = wm * 32 + mi * 16 + g;
            uint32_t aH0 = AsH[t][mb],   aH1 = AsH[t][mb+8];
            uint32_t aH2 = AsH[t+4][mb], aH3 = AsH[t+4][mb+8];
            uint32_t aL0 = AsL[t][mb],   aL1 = AsL[t][mb+8];
            uint32_t aL2 = AsL[t+4][mb], aL3 = AsL[t+4][mb+8];
            #pragma unroll
            for (int nj = 0; nj < NJ; nj++) {
                MMA_BF16(acc[mi][nj], aH0,aH1,aH2,aH3, bH[nj][0], bH[nj][1]);
                MMA_BF16(acc[mi][nj], aL0,aL1,aL2,aL3, bH[nj][0], bH[nj][1]);
                MMA_BF16(acc[mi][nj], aH0,aH1,aH2,aH3, bL[nj][0], bL[nj][1]);
            }
        }
    };

    ldA(0, rA0);  ldB(0, rB0);
    ldA(16, rA1); ldB(16, rB1);

    #pragma unroll 1
    for (int k0 = 0; k0 < KT; k0 += 32) {
        stA(rA0); stB(rB0);
        __syncthreads();
        ldA(k0 + 32, rA0); ldB(k0 + 32, rB0);
        compute();
        __syncthreads();
        stA(rA1); stB(rB1);
        __syncthreads();
        ldA(k0 + 48, rA1); ldB(k0 + 48, rB1);
        compute();
        __syncthreads();
    }

    // epilogue
    #pragma unroll
    for (int mi = 0; mi < 2; mi++) {
        int r = row0 + wm * 32 + mi * 16 + g;
        #pragma unroll
        for (int nj = 0; nj < NJ; nj++) {
            int cl = n0 + nj * 8 + 2 * t;
            float v00 = acc[mi][nj][0], v01 = acc[mi][nj][1];
            float v10 = acc[mi][nj][2], v11 = acc[mi][nj][3];
            if (MODE == 2) {
                atomicAdd(&Cp[r * P + cl],           v00);
                atomicAdd(&Cp[r * P + cl + 1],       v01);
                atomicAdd(&Cp[(r + 8) * P + cl],     v10);
                atomicAdd(&Cp[(r + 8) * P + cl + 1], v11);
            } else {
                if (bias) {
                    float b0 = bias[cl], b1 = bias[cl + 1];
                    v00 += b0; v01 += b1; v10 += b0; v11 += b1;
                }
                *(float2*)&Cp[(long)r * ldc + col0 + cl]       = make_float2(v00, v01);
                *(float2*)&Cp[(long)(r + 8) * ldc + col0 + cl] = make_float2(v10, v11);
            }
        }
    }
}

// ---------------- launch ----------------
extern "C" void kernel_launch(void* const* d_in, const int* in_sizes, int n_in,
                              void* d_out, int out_size)
{
    const float* x    = (const float*)d_in[0];
    const float* WQ   = (const float*)d_in[1];
    const float* WK   = (const float*)d_in[2];
    const float* WV   = (const float*)d_in[3];
    const float* RW   = (const float*)d_in[4];
    const float* pw   = (const float*)d_in[5];
    const float* pb   = (const float*)d_in[6];
    const float* q1v  = (const float*)d_in[7];
    const float* k1v  = (const float*)d_in[8];
    const float* q2v  = (const float*)d_in[9];
    const float* k2v  = (const float*)d_in[10];
    const float* lam0 = (const float*)d_in[11];
    float* out = (float*)d_out;

    float *Wf, *qkv, *Mb, *G, *Weff;
    cudaGetSymbolAddress((void**)&Wf,   g_Wf);
    cudaGetSymbolAddress((void**)&qkv,  g_qkv);
    cudaGetSymbolAddress((void**)&Mb,   g_M);
    cudaGetSymbolAddress((void**)&G,    g_G);
    cudaGetSymbolAddress((void**)&Weff, g_Weff);

    // 1. Weff + lambda + zero M
    k_misc<<<257, 256>>>(RW, q1v, k1v, q2v, k2v, lam0);

    // 2. Wf[:, z*64:(z+1)*64] = {WQ,WK,WV}[z] @ pw
    mmk<64, 1, 1024><<<dim3(1, 16, 3), 256>>>(
        WQ, WK, WV, E, 0,  pw, P, 0,  Wf, QKV_LD, 0, nullptr);

    // 3. qkv = x @ Wf + bias
    mmk<128, 0, 1024><<<dim3(3, 32, 1), 256>>>(
        x, nullptr, nullptr, E, 0,  Wf, QKV_LD, 0,  qkv, QKV_LD, 0, pb);

    // 4. M_b += k_chunk^T @ v_chunk  (split-K over 16 chunks of 128 tokens)
    mmk<64, 2, 128><<<dim3(16, 1, 2), 256>>>(
        nullptr, nullptr, nullptr, 0, 0,  nullptr, 0, 0,  Mb, P, 0, nullptr);

    // 5. G_b = (D M_b) @ Weff
    mmk<64, 3, 64><<<dim3(16, 1, 2), 256>>>(
        Mb, nullptr, nullptr, P, (long)P * P,  Weff, E, 0,
        G, E, (long)P * E, nullptr);

    // 6. out_b = q_b @ G_b
    mmk<128, 0, 64><<<dim3(16, 16, 2), 256>>>(
        qkv, nullptr, nullptr, QKV_LD, (long)SEQ * QKV_LD,  G, E, (long)P * E,
        out, E, (long)SEQ * E, nullptr);

    (void)in_sizes; (void)n_in; (void)out_size;
}

// round 5
// speedup vs baseline: 3.3094x; 1.2109x over previous
#include <cuda_runtime.h>
#include <cuda_bf16.h>
#include <math.h>
#include <stdint.h>

#define E 1024
#define NH 16
#define P 64
#define BATCH 2
#define SEQ 2048
#define BS (BATCH*SEQ)          // 4096
#define QKV_LD 192

// ---------------- device scratch ----------------
__device__ float g_lam;
__device__ float g_Wf[E*QKV_LD];       // [1024,192]
__device__ float g_Weff[P*E];          // [64,1024]
__device__ float g_qkv[BS*QKV_LD];     // [4096,192]
__device__ float g_M[BATCH*P*P];       // [2,64,64]
__device__ float g_qp[BS*P];           // [4096,64]

// ---------------- helpers ----------------
__device__ __forceinline__ void split2(float x0, float x1, uint32_t& hi, uint32_t& lo) {
    __nv_bfloat162 h = __floats2bfloat162_rn(x0, x1);
    hi = *(uint32_t*)&h;
    __nv_bfloat162 l = __floats2bfloat162_rn(x0 - __bfloat162float(h.x),
                                             x1 - __bfloat162float(h.y));
    lo = *(uint32_t*)&l;
}

#define MMA_BF16(d, a0,a1,a2,a3, b0,b1) \
    asm volatile("mma.sync.aligned.m16n8k16.row.col.f32.bf16.bf16.f32 " \
        "{%0,%1,%2,%3}, {%4,%5,%6,%7}, {%8,%9}, {%0,%1,%2,%3};" \
        : "+f"(d[0]),"+f"(d[1]),"+f"(d[2]),"+f"(d[3]) \
        : "r"(a0),"r"(a1),"r"(a2),"r"(a3), "r"(b0),"r"(b1))

// ================= prep: Weff + lambda + zero M + zero Wf =================
__global__ void k_prep(const float* __restrict__ RW,
                       const float* __restrict__ q1v, const float* __restrict__ k1v,
                       const float* __restrict__ q2v, const float* __restrict__ k2v,
                       const float* __restrict__ lam0)
{
    const int bid = blockIdx.x;
    const int tid = threadIdx.x;
    if (bid < 256) {
        int idx = bid * 256 + tid;                 // 65536 total
        int q = idx >> 10, e = idx & 1023;
        float s = 0.f;
        #pragma unroll
        for (int h = 0; h < NH; h++)
            s = fmaf((float)(h + 1), RW[(size_t)((h << 6) + q) * E + e], s);
        g_Weff[idx] = s;
    } else if (bid == 256) {
        __shared__ float s1[256], s2[256];
        float a = 0.f, b = 0.f;
        for (int i = tid; i < E; i += 256) {
            a = fmaf(q1v[i], k1v[i], a);
            b = fmaf(q2v[i], k2v[i], b);
        }
        s1[tid] = a; s2[tid] = b; __syncthreads();
        for (int o = 128; o > 0; o >>= 1) {
            if (tid < o) { s1[tid] += s1[tid+o]; s2[tid] += s2[tid+o]; }
            __syncthreads();
        }
        if (tid == 0) g_lam = expf(s1[0]) - expf(s2[0]) + lam0[0];
        for (int i = tid; i < BATCH*P*P; i += 256) g_M[i] = 0.f;
    } else {
        // zero Wf: 192 blocks x 256 threads x float4 = 196608 floats
        int idx = (bid - 257) * 256 + tid;
        ((float4*)g_Wf)[idx] = make_float4(0.f, 0.f, 0.f, 0.f);
    }
}

// ================= generic bf16-3pass tensor GEMM =================
// MODE 0: plain (+bias), batched by z via strides
// MODE 1: Wf split-K: A = {A0,A1,A2}[z], k-chunk = bx*KT, atomicAdd into C + z*64
// MODE 2: ktv: A = k^T slice of g_qkv (gather), B = v slice, atomicAdd into g_M
// MODE 3: q' = q @ (D M_b): B rows scaled by s_k
template<int BM, int MODE, int KT>
__global__ void __launch_bounds__(256) mmk(
    const float* __restrict__ A0, const float* __restrict__ A1, const float* __restrict__ A2,
    int lda, long sA,
    const float* __restrict__ B0, int ldb, long sB,
    float* __restrict__ C, int ldc, long sC,
    const float* __restrict__ bias)
{
    constexpr int AST = (BM == 128) ? 136 : 72;
    __shared__ uint32_t AsH[8][AST], AsL[8][AST];
    __shared__ uint32_t BsH[8][72],  BsL[8][72];

    const int z   = blockIdx.z;
    const int tid = threadIdx.x;

    const float* A = A0;
    const float* B = B0;
    float* Cp = C;
    const float* Aq = nullptr;
    const float* Bq = nullptr;
    int ldbv = ldb;
    int row0, col0;
    if (MODE == 1) {
        A = ((z == 0) ? A0 : (z == 1) ? A1 : A2) + blockIdx.x * KT;  // k-chunk col offset
        B = B0 + (long)(blockIdx.x * KT) * ldb;
        Cp = C + z * 64;
        row0 = blockIdx.y * BM; col0 = 0;
    } else if (MODE == 2) {
        Aq = g_qkv + (long)(z * SEQ + blockIdx.x * 64) * QKV_LD;
        Bq = Aq + 128;
        Cp = C + z * P * P;
        ldbv = QKV_LD;
        row0 = 0; col0 = 0;
    } else {
        A  = A0 + (long)z * sA;
        B  = B0 + (long)z * sB;
        Cp = C  + (long)z * sC;
        row0 = blockIdx.y * BM; col0 = blockIdx.x * 64;
    }

    constexpr int WM = (BM == 128) ? 4 : 2;
    constexpr int WCOL = 64 / (8 / WM);
    constexpr int NJ = WCOL / 8;
    const int wid = tid >> 5, lane = tid & 31;
    const int wm = wid % WM, wn = wid / WM;
    const int g = lane >> 2, t = lane & 3;
    const int n0 = wn * WCOL;

    const int m_l  = (MODE == 2) ? (tid & 63) : ((BM == 128) ? (tid >> 1) : (tid >> 2));
    const int khA  = (MODE == 2) ? ((tid >> 6) * 4) : ((BM == 128) ? (tid & 1) * 8 : (tid & 3) * 4);
    const int khA2 = khA >> 1;
    const int k2b  = tid >> 5;
    const int n2   = (tid & 31) * 2;

    const float lam = (MODE == 3) ? g_lam : 0.f;

    constexpr int AR = (BM == 128) ? 8 : 4;
    float rA0[AR], rA1[AR], rB0[4], rB1[4];

    auto ldA = [&](int k0, float* r) {
        int kk = (k0 < KT) ? k0 : 0;
        if (MODE == 2) {
            const float* p = Aq + (long)(kk + khA) * QKV_LD + 64 + m_l;
            #pragma unroll
            for (int j = 0; j < 4; j++) r[j] = p[j * QKV_LD];
        } else if (BM == 128) {
            const float* p = A + (long)(row0 + m_l) * lda + kk + khA;
            float4 v0 = *(const float4*)p;
            float4 v1 = *(const float4*)(p + 4);
            r[0]=v0.x; r[1]=v0.y; r[2]=v0.z; r[3]=v0.w;
            r[4]=v1.x; r[5]=v1.y; r[6]=v1.z; r[7]=v1.w;
        } else {
            float4 v0 = *(const float4*)(A + (long)(row0 + m_l) * lda + kk + khA);
            r[0]=v0.x; r[1]=v0.y; r[2]=v0.z; r[3]=v0.w;
        }
    };
    auto ldB = [&](int k0, float* r) {
        int kk = (k0 < KT) ? k0 : 0;
        const float* bp = (MODE == 2) ? Bq : (B + col0);
        float2 e0 = *(const float2*)(bp + (long)(kk + 2*k2b)     * ldbv + n2);
        float2 e1 = *(const float2*)(bp + (long)(kk + 2*k2b + 1) * ldbv + n2);
        if (MODE == 3) {
            float s = ((kk + 2*k2b) < 32) ? 0.125f : (-lam * 0.125f);
            e0.x *= s; e0.y *= s; e1.x *= s; e1.y *= s;
        }
        r[0]=e0.x; r[1]=e0.y; r[2]=e1.x; r[3]=e1.y;
    };
    auto stA = [&](const float* r) {
        #pragma unroll
        for (int j = 0; j < AR/2; j++)
            split2(r[2*j], r[2*j+1], AsH[khA2 + j][m_l], AsL[khA2 + j][m_l]);
    };
    auto stB = [&](const float* r) {
        split2(r[0], r[2], BsH[k2b][n2],   BsL[k2b][n2]);
        split2(r[1], r[3], BsH[k2b][n2+1], BsL[k2b][n2+1]);
    };

    float acc[2][NJ][4] = {};

    auto compute = [&]() {
        uint32_t bH[NJ][2], bL[NJ][2];
        #pragma unroll
        for (int nj = 0; nj < NJ; nj++) {
            int nb = n0 + nj * 8 + g;
            bH[nj][0] = BsH[t][nb]; bH[nj][1] = BsH[t+4][nb];
            bL[nj][0] = BsL[t][nb]; bL[nj][1] = BsL[t+4][nb];
        }
        #pragma unroll
        for (int mi = 0; mi < 2; mi++) {
            int mb = wm * 32 + mi * 16 + g;
            uint32_t aH0 = AsH[t][mb],   aH1 = AsH[t][mb+8];
            uint32_t aH2 = AsH[t+4][mb], aH3 = AsH[t+4][mb+8];
            uint32_t aL0 = AsL[t][mb],   aL1 = AsL[t][mb+8];
            uint32_t aL2 = AsL[t+4][mb], aL3 = AsL[t+4][mb+8];
            #pragma unroll
            for (int nj = 0; nj < NJ; nj++) {
                MMA_BF16(acc[mi][nj], aH0,aH1,aH2,aH3, bH[nj][0], bH[nj][1]);
                MMA_BF16(acc[mi][nj], aL0,aL1,aL2,aL3, bH[nj][0], bH[nj][1]);
                MMA_BF16(acc[mi][nj], aH0,aH1,aH2,aH3, bL[nj][0], bL[nj][1]);
            }
        }
    };

    ldA(0, rA0);  ldB(0, rB0);
    ldA(16, rA1); ldB(16, rB1);

    #pragma unroll 1
    for (int k0 = 0; k0 < KT; k0 += 32) {
        stA(rA0); stB(rB0);
        __syncthreads();
        ldA(k0 + 32, rA0); ldB(k0 + 32, rB0);
        compute();
        __syncthreads();
        stA(rA1); stB(rB1);
        __syncthreads();
        ldA(k0 + 48, rA1); ldB(k0 + 48, rB1);
        compute();
        __syncthreads();
    }

    #pragma unroll
    for (int mi = 0; mi < 2; mi++) {
        int r = row0 + wm * 32 + mi * 16 + g;
        #pragma unroll
        for (int nj = 0; nj < NJ; nj++) {
            int cl = n0 + nj * 8 + 2 * t;
            float v00 = acc[mi][nj][0], v01 = acc[mi][nj][1];
            float v10 = acc[mi][nj][2], v11 = acc[mi][nj][3];
            if (MODE == 1 || MODE == 2) {
                int ld = (MODE == 2) ? P : ldc;
                atomicAdd(&Cp[(long)r * ld + cl],           v00);
                atomicAdd(&Cp[(long)r * ld + cl + 1],       v01);
                atomicAdd(&Cp[(long)(r + 8) * ld + cl],     v10);
                atomicAdd(&Cp[(long)(r + 8) * ld + cl + 1], v11);
            } else {
                if (bias) {
                    float b0 = bias[cl], b1 = bias[cl + 1];
                    v00 += b0; v01 += b1; v10 += b0; v11 += b1;
                }
                *(float2*)&Cp[(long)r * ldc + col0 + cl]       = make_float2(v00, v01);
                *(float2*)&Cp[(long)(r + 8) * ldc + col0 + cl] = make_float2(v10, v11);
            }
        }
    }
}

// ---------------- launch ----------------
extern "C" void kernel_launch(void* const* d_in, const int* in_sizes, int n_in,
                              void* d_out, int out_size)
{
    const float* x    = (const float*)d_in[0];
    const float* WQ   = (const float*)d_in[1];
    const float* WK   = (const float*)d_in[2];
    const float* WV   = (const float*)d_in[3];
    const float* RW   = (const float*)d_in[4];
    const float* pw   = (const float*)d_in[5];
    const float* pb   = (const float*)d_in[6];
    const float* q1v  = (const float*)d_in[7];
    const float* k1v  = (const float*)d_in[8];
    const float* q2v  = (const float*)d_in[9];
    const float* k2v  = (const float*)d_in[10];
    const float* lam0 = (const float*)d_in[11];
    float* out = (float*)d_out;

    float *Wf, *qkv, *Mb, *qp, *Weff;
    cudaGetSymbolAddress((void**)&Wf,   g_Wf);
    cudaGetSymbolAddress((void**)&qkv,  g_qkv);
    cudaGetSymbolAddress((void**)&Mb,   g_M);
    cudaGetSymbolAddress((void**)&qp,   g_qp);
    cudaGetSymbolAddress((void**)&Weff, g_Weff);

    // 1. Weff + lambda + zero M + zero Wf
    k_prep<<<449, 256>>>(RW, q1v, k1v, q2v, k2v, lam0);

    // 2. Wf split-K x4: grid (kz=4, y=16, z=3) = 192 blocks
    mmk<64, 1, 256><<<dim3(4, 16, 3), 256>>>(
        WQ, WK, WV, E, 0,  pw, P, 0,  Wf, QKV_LD, 0, nullptr);

    // 3. qkv = x @ Wf + bias : grid (3, 64) = 192 blocks
    mmk<64, 0, 1024><<<dim3(3, 64, 1), 256>>>(
        x, nullptr, nullptr, E, 0,  Wf, QKV_LD, 0,  qkv, QKV_LD, 0, pb);

    // 4. M_b += k_chunk^T @ v_chunk : 32 chunks of 64 tokens, grid 64
    mmk<64, 2, 64><<<dim3(32, 1, 2), 256>>>(
        nullptr, nullptr, nullptr, 0, 0,  nullptr, 0, 0,  Mb, P, 0, nullptr);

    // 5. q'_b = q_b @ (D M_b) : grid (1, 32, 2) = 64 blocks
    mmk<64, 3, 64><<<dim3(1, 32, 2), 256>>>(
        qkv, nullptr, nullptr, QKV_LD, (long)SEQ * QKV_LD,  Mb, P, (long)P * P,
        qp, P, (long)SEQ * P, nullptr);

    // 6. out = q' @ Weff : single [4096,64]@[64,1024], grid (16, 32) = 512
    mmk<128, 0, 64><<<dim3(16, 32, 1), 256>>>(
        qp, nullptr, nullptr, P, 0,  Weff, E, 0,
        out, E, 0, nullptr);

    (void)in_sizes; (void)n_in; (void)out_size;
}